// round 9
// baseline (speedup 1.0000x reference)
#include <cuda_runtime.h>
#include <math.h>

#define NSTEPS 130
#define NLUT   27
#define ROWS   32
#define UROWS  132          // 130 data rows + 2 padding rows for tail prefetch

// srcA[l] / srcB[l]: flat-state index feeding mux selects A / B of LUT-lane l.
// Lanes 27..31 are constant-carrier lanes (self-wired).
__device__ __constant__ int c_srcA[32] = {
    1, 3, 3,   7, 0, 0,   4, 6, 6,   19, 12, 12,  16, 9, 9,
    13, 15, 15, 10, 18, 18, 22, 6, 6, 25, 15, 15,
    27, 28, 29, 30, 31};
__device__ __constant__ int c_srcB[32] = {
    17, 17, 1,  5, 5, 7,   11, 11, 4, 8, 8, 19,   28, 28, 16,
    2, 2, 13,   27, 27, 10, 23, 23, 22, 26, 26, 25,
    27, 28, 29, 30, 31};

#define BAR_ARRIVE(b, n) asm volatile("bar.arrive %0, %1;" :: "n"(b), "n"(n) : "memory")
#define BAR_WAIT(b, n)   asm volatile("bar.sync %0, %1;"   :: "n"(b), "n"(n) : "memory")

__global__ void one_layer_net_kernel(const float* __restrict__ x,
                                     const float* __restrict__ weights,
                                     const float4* __restrict__ noise4,
                                     float* __restrict__ out) {
    extern __shared__ float4 s_uvrs[];   // [132][32] quadruples

    const int tid  = threadIdx.x;
    const int wrp  = tid >> 5;
    const int lane = tid & 31;

    if (wrp > 0) {
        // ------------------- PRODUCER WARPS (1..7) -------------------------
        // Row map: warp1 -> rows 0..3 then 124..129 (+2 pad rows),
        //          warp2 -> 4..23, warp3 -> 24..43, warp4 -> 44..63,
        //          warp5 -> 64..83, warp6 -> 84..103, warp7 -> 104..123.
        const bool act = (lane < NLUT);
        const int  nl  = act ? lane : 0;

        float4 wb = make_float4(0.f, 0.f, 0.f, 0.f);
        float c0, c1, c2, c3, xv;

        if (wrp == 1) {
            // Front-batch ALL 10 noise LDGs (rows 0..3 and 124..129) first.
            float4 nb[10];
#pragma unroll
            for (int i = 0; i < 4; ++i)  nb[i]     = noise4[i * NLUT + nl];
#pragma unroll
            for (int i = 0; i < 6; ++i)  nb[4 + i] = noise4[(124 + i) * NLUT + nl];

            if (act) wb = reinterpret_cast<const float4*>(weights)[lane];
            c0 = fabsf(1.0f - fabsf(wb.x)) * 0.125f;
            c1 = fabsf(1.0f - fabsf(wb.y)) * 0.125f;
            c2 = fabsf(1.0f - fabsf(wb.z)) * 0.125f;
            c3 = fabsf(1.0f - fabsf(wb.w)) * 0.125f;
            xv = (lane == 27) ? x[0] : ((lane == 28) ? x[1] : 0.0f);

#pragma unroll
            for (int i = 0; i < 10; ++i) {
                const float4 n = nb[i];
                const int row = (i < 4) ? i : (120 + i);   // 0..3, 124..129
                const float w0 = fmaf(c0, n.x, wb.x);
                const float w1 = fmaf(c1, n.y, wb.y);
                const float w2 = fmaf(c2, n.z, wb.z);
                const float w3 = fmaf(c3, n.w, wb.w);
                const float d01 = w1 - w0, d23 = w3 - w2;
                const float p01 = w0 + w1, p23 = w2 + w3;
                float4 q;
                q.x = act ? 0.25f * (d23 - d01) : 0.f;
                q.y = act ? 0.25f * (p23 - p01) : 0.f;
                q.z = act ? 0.25f * (d01 + d23) : 0.f;
                q.w = act ? 0.25f * (p01 + p23) : xv;
                s_uvrs[row * ROWS + lane] = q;
                if (i == 3) { BAR_ARRIVE(1, 64); }   // rows 0..3 ready
            }
            s_uvrs[130 * ROWS + lane] = make_float4(0.f, 0.f, 0.f, 0.f);
            s_uvrs[131 * ROWS + lane] = make_float4(0.f, 0.f, 0.f, 0.f);
            BAR_ARRIVE(4, 160);                      // rows 124..131 ready
            return;
        }

        const int s0 = 4 + 20 * (wrp - 2);

        // Front-batch this warp's 20 noise loads (max MLP) before weights.
        float4 nbuf[20];
#pragma unroll
        for (int i = 0; i < 20; ++i)
            nbuf[i] = noise4[(s0 + i) * NLUT + nl];

        if (act) wb = reinterpret_cast<const float4*>(weights)[lane];
        c0 = fabsf(1.0f - fabsf(wb.x)) * 0.125f;
        c1 = fabsf(1.0f - fabsf(wb.y)) * 0.125f;
        c2 = fabsf(1.0f - fabsf(wb.z)) * 0.125f;
        c3 = fabsf(1.0f - fabsf(wb.w)) * 0.125f;
        xv = (lane == 27) ? x[0] : ((lane == 28) ? x[1] : 0.0f);

#pragma unroll
        for (int i = 0; i < 20; ++i) {
            const float4 n = nbuf[i];
            const float w0 = fmaf(c0, n.x, wb.x);
            const float w1 = fmaf(c1, n.y, wb.y);
            const float w2 = fmaf(c2, n.z, wb.z);
            const float w3 = fmaf(c3, n.w, wb.w);
            const float d01 = w1 - w0, d23 = w3 - w2;
            const float p01 = w0 + w1, p23 = w2 + w3;
            float4 q;
            q.x = act ? 0.25f * (d23 - d01) : 0.f;
            q.y = act ? 0.25f * (p23 - p01) : 0.f;
            q.z = act ? 0.25f * (d01 + d23) : 0.f;
            q.w = act ? 0.25f * (p01 + p23) : xv;
            s_uvrs[(s0 + i) * ROWS + lane] = q;
        }
        // bar2: warp2 alone (64). bar3: warps 3+4 (96). bar4: warps 5..7 +
        // warp1-pass2 (160).
        if (wrp == 2)      { BAR_ARRIVE(2, 64); }
        else if (wrp <= 4) { BAR_ARRIVE(3, 96); }
        else               { BAR_ARRIVE(4, 160); }
        return;
    }

    // ----------------------- CONSUMER WARP (0) -----------------------------
    const int sa = c_srcA[lane];
    const int sb = c_srcB[lane];
    const int aa = c_srcA[sa], ba = c_srcB[sa];
    const int ab = c_srcA[sb], bb = c_srcB[sb];

    float state = (lane < NLUT) ? -1.0f
                : (lane == 27) ? x[0]
                : (lane == 28) ? x[1] : 0.0f;

    BAR_WAIT(1, 64);   // rows 0..3 ready

    const float4* pAp = s_uvrs + sa;
    const float4* pBp = s_uvrs + sb;
    const float4* pFp = s_uvrs + ROWS + lane;
    float4 cA = pAp[0];
    float4 cB = pBp[0];
    float4 cF = pFp[0];
    pAp += 2 * ROWS; pBp += 2 * ROWS; pFp += 2 * ROWS;

#define SCAN_ITER()                                                          \
    do {                                                                     \
        const float4 pA = pAp[0];                                            \
        const float4 pB = pBp[0];                                            \
        const float4 pF = pFp[0];                                            \
        pAp += 2 * ROWS; pBp += 2 * ROWS; pFp += 2 * ROWS;                   \
        const float aAv = __shfl_sync(0xFFFFFFFFu, state, aa);               \
        const float bAv = __shfl_sync(0xFFFFFFFFu, state, ba);               \
        const float aBv = __shfl_sync(0xFFFFFFFFu, state, ab);               \
        const float bBv = __shfl_sync(0xFFFFFFFFu, state, bb);               \
        const float iA = fmaf(bAv, fmaf(aAv, cA.x, cA.y),                    \
                              fmaf(aAv, cA.z, cA.w));                        \
        const float iB = fmaf(bBv, fmaf(aBv, cB.x, cB.y),                    \
                              fmaf(aBv, cB.z, cB.w));                        \
        state = fmaf(iB, fmaf(iA, cF.x, cF.y), fmaf(iA, cF.z, cF.w));        \
        cA = pA; cB = pB; cF = pF;                                           \
    } while (0)

    // iter k consumes rows 2k,2k+1 and prefetches rows 2k+2,2k+3:
    //   k=0      needs rows <=3    (bar 1, passed)
    //   k=1..10  needs rows <=23   (bar 2: warp2)
    //   k=11..30 needs rows <=63   (bar 3: warps 3+4)
    //   k=31..64 needs rows <=131  (bar 4: warps 5..7 + warp1 pass 2)
    SCAN_ITER();
    BAR_WAIT(2, 64);
#pragma unroll
    for (int i = 0; i < 10; ++i) SCAN_ITER();
    BAR_WAIT(3, 96);
#pragma unroll
    for (int i = 0; i < 20; ++i) SCAN_ITER();
    BAR_WAIT(4, 160);
#pragma unroll
    for (int i = 0; i < 34; ++i) SCAN_ITER();

    // Outputs: final[0,1] -> flat 1, final[1,2] -> flat 5, final[7,2] -> flat 23.
    if (lane == 1)  out[0] = state;
    if (lane == 5)  out[1] = state;
    if (lane == 23) out[2] = state;
}

extern "C" void kernel_launch(void* const* d_in, const int* in_sizes, int n_in,
                              void* d_out, int out_size) {
    (void)in_sizes; (void)n_in; (void)out_size;
    const float*  x  = (const float*)d_in[0];      // [2]
    const float*  w  = (const float*)d_in[1];      // [9,3,4]
    const float4* nz = (const float4*)d_in[2];     // [130,9,3,4] as float4
    float* out = (float*)d_out;                    // [3]

    const size_t smem = (size_t)UROWS * ROWS * sizeof(float4);   // 67584 B
    cudaFuncSetAttribute(one_layer_net_kernel,
                         cudaFuncAttributeMaxDynamicSharedMemorySize, (int)smem);
    one_layer_net_kernel<<<1, 256, smem>>>(x, w, nz, out);
}